// round 4
// baseline (speedup 1.0000x reference)
#include <cuda_runtime.h>
#include <math.h>

#define NB 32
#define CD 64
#define TPB 128
#define RPB 256            // rows per block; 4 rows per thread-pair, 64 pairs
#define CHUNK_D 32
#define NCHUNK (CD / CHUNK_D)

// ---- packed fp32x2 helpers (Blackwell) ----
__device__ __forceinline__ void fma2(unsigned long long& d,
                                     unsigned long long a,
                                     unsigned long long b) {
    asm("fma.rn.f32x2 %0, %1, %2, %0;" : "+l"(d) : "l"(a), "l"(b));
}
__device__ __forceinline__ unsigned long long splat2(float x) {
    unsigned long long r;
    unsigned int u = __float_as_uint(x);
    asm("mov.b64 %0, {%1, %1};" : "=l"(r) : "r"(u));
    return r;
}
__device__ __forceinline__ void unpack2(unsigned long long v, float& lo, float& hi) {
    unsigned int a, b;
    asm("mov.b64 {%0, %1}, %2;" : "=r"(a), "=r"(b) : "l"(v));
    lo = __uint_as_float(a);
    hi = __uint_as_float(b);
}

__global__ void gc_init_util(const float* __restrict__ u_in,
                             float* __restrict__ u_out) {
    int i = threadIdx.x;
    if (i < NB) u_out[i] = u_in[i];
}

__global__ __launch_bounds__(TPB, 5)
void gc_main(const float* __restrict__ z,
             const float* __restrict__ protos,
             float* __restrict__ act,
             float* __restrict__ assign,
             float* __restrict__ util,
             int B) {
    __shared__ float4      s_z[RPB * (CHUNK_D / 4)];   // 32 KB, XOR swizzle on row
    __shared__ ulonglong2  s_pp[CD * 8];               // 8 KB: [d][8x ull2] = 16 basin-pairs
    __shared__ float4      s_res[RPB];                 // 4 KB
    __shared__ int         s_hist[NB];

    const int tid  = threadIdx.x;
    const int base = blockIdx.x * RPB;
    const int p    = tid >> 1;          // pair id 0..63
    const int half = tid & 1;           // 0: basins 0-15, 1: basins 16-31

    // ---- packed prototype table: float2[d*16+k] = (proto[2k][d], proto[2k+1][d])
    {
        float2* f2 = (float2*)s_pp;
        #pragma unroll
        for (int it = 0; it < (CD * 16) / TPB; it++) {
            int idx = it * TPB + tid;
            int d = idx >> 4;
            int k = idx & 15;
            f2[idx] = make_float2(protos[(2 * k) * CD + d],
                                  protos[(2 * k + 1) * CD + d]);
        }
        if (tid < NB) s_hist[tid] = 0;
    }

    // acc[j*8+k]: row j (local row p + j*64), basin pair (half*8 + k)
    unsigned long long acc[32];
    #pragma unroll
    for (int j = 0; j < 32; j++) acc[j] = 0ull;

    const int pk7 = p & 7;

    for (int c = 0; c < NCHUNK; c++) {
        __syncthreads();
        // stage z chunk: coalesced LDG.128, swizzled STS
        #pragma unroll
        for (int it = 0; it < (RPB * (CHUNK_D / 4)) / TPB; it++) {
            int idx   = it * TPB + tid;
            int row_l = idx >> 3;
            int d4    = idx & 7;
            int grow  = base + row_l;
            if (grow < B) {
                float4 v = *(const float4*)(z + (size_t)grow * CD + c * CHUNK_D + d4 * 4);
                s_z[row_l * 8 + (d4 ^ (row_l & 7))] = v;
            }
        }
        __syncthreads();

        #pragma unroll 2
        for (int d4 = 0; d4 < 8; d4++) {
            const int col = d4 ^ pk7;
            float4 z0 = s_z[(p +   0) * 8 + col];
            float4 z1 = s_z[(p +  64) * 8 + col];
            float4 z2 = s_z[(p + 128) * 8 + col];
            float4 z3 = s_z[(p + 192) * 8 + col];
            float e0[4] = {z0.x, z0.y, z0.z, z0.w};
            float e1[4] = {z1.x, z1.y, z1.z, z1.w};
            float e2[4] = {z2.x, z2.y, z2.z, z2.w};
            float e3[4] = {z3.x, z3.y, z3.z, z3.w};
            #pragma unroll
            for (int e = 0; e < 4; e++) {
                const int d = c * CHUNK_D + d4 * 4 + e;
                const ulonglong2* pp = &s_pp[d * 8 + half * 4];
                const unsigned long long za = splat2(e0[e]);
                const unsigned long long zb = splat2(e1[e]);
                const unsigned long long zc = splat2(e2[e]);
                const unsigned long long zd = splat2(e3[e]);
                #pragma unroll
                for (int q = 0; q < 4; q++) {
                    ulonglong2 w = pp[q];            // 2 basin pairs (16B, 2 addrs/warp)
                    fma2(acc[0 * 8 + 2 * q],     za, w.x);
                    fma2(acc[0 * 8 + 2 * q + 1], za, w.y);
                    fma2(acc[1 * 8 + 2 * q],     zb, w.x);
                    fma2(acc[1 * 8 + 2 * q + 1], zb, w.y);
                    fma2(acc[2 * 8 + 2 * q],     zc, w.x);
                    fma2(acc[2 * 8 + 2 * q + 1], zc, w.y);
                    fma2(acc[3 * 8 + 2 * q],     zd, w.x);
                    fma2(acc[3 * 8 + 2 * q + 1], zd, w.y);
                }
            }
        }
    }

    // ---- per-row: local top-3 over own 16 basins, shfl-merge with partner
    #pragma unroll
    for (int j = 0; j < 4; j++) {
        const int rl  = p + j * 64;
        const bool ok = (base + rl) < B;

        float v[16];
        #pragma unroll
        for (int k = 0; k < 8; k++)
            unpack2(acc[j * 8 + k], v[2 * k], v[2 * k + 1]);

        float l0 = -2.0f, l1 = -2.0f, l2 = -2.0f;
        int   j0 = 0,     j1 = 0,     j2 = 0;
        #pragma unroll
        for (int n = 0; n < 16; n++) {
            const float x = v[n];
            if (x > l2) {
                if (x > l1) {
                    if (x > l0) { l2 = l1; j2 = j1; l1 = l0; j1 = j0; l0 = x; j0 = n; }
                    else        { l2 = l1; j2 = j1; l1 = x;  j1 = n; }
                } else          { l2 = x;  j2 = n; }
            }
        }
        const int g0 = j0 + (half << 4);
        const int g1 = j1 + (half << 4);
        const int g2 = j2 + (half << 4);

        // exchange with partner lane
        const float q0 = __shfl_xor_sync(0xFFFFFFFFu, l0, 1);
        const float q1 = __shfl_xor_sync(0xFFFFFFFFu, l1, 1);
        const float q2 = __shfl_xor_sync(0xFFFFFFFFu, l2, 1);
        const int   qp = __shfl_xor_sync(0xFFFFFFFFu, g0 | (g1 << 8) | (g2 << 16), 1);

        // a = low-half candidates (ties prefer a, matching stable top_k)
        const float a0 = half ? q0 : l0, a1 = half ? q1 : l1, a2 = half ? q2 : l2;
        const float b0 = half ? l0 : q0, b1 = half ? l1 : q1, b2 = half ? l2 : q2;
        const int ia0 = half ? (qp & 255)        : g0;
        const int ia1 = half ? ((qp >> 8) & 255) : g1;
        const int ia2 = half ? ((qp >> 16) & 255): g2;
        const int ib0 = half ? g0 : (qp & 255);
        const int ib1 = half ? g1 : ((qp >> 8) & 255);
        const int ib2 = half ? g2 : ((qp >> 16) & 255);

        // 3-way merge of two sorted triples, a wins ties
        const bool s0 = (a0 >= b0);
        const float m0 = s0 ? a0 : b0;  const int mi0 = s0 ? ia0 : ib0;
        const float ha = s0 ? a1 : a0;  const int hai = s0 ? ia1 : ia0;
        const float hb = s0 ? b0 : b1;  const int hbi = s0 ? ib0 : ib1;
        const bool s1 = (ha >= hb);
        const float m1 = s1 ? ha : hb;  const int mi1 = s1 ? hai : hbi;
        const float ha2 = s1 ? (s0 ? a2 : a1) : ha;
        const int   hai2= s1 ? (s0 ? ia2: ia1): hai;
        const float hb2 = s1 ? hb : (s0 ? b1 : b2);
        const int   hbi2= s1 ? hbi: (s0 ? ib1: ib2);
        const bool s2 = (ha2 >= hb2);
        const float m2 = s2 ? ha2 : hb2; const int mi2 = s2 ? hai2 : hbi2;

        if (half == 0 && ok) {
            const float x1  = __expf((m1 - m0) * 0.2f);
            const float x2  = __expf((m2 - m0) * 0.2f);
            const float inv = 1.0f / (1.0f + x1 + x2);
            s_res[rl] = make_float4(inv, x1 * inv, x2 * inv,
                                    __int_as_float(mi0 | (mi1 << 8) | (mi2 << 16)));
            atomicAdd(&s_hist[mi0], 1);
        }
    }
    __syncthreads();

    // ---- coalesced act stores: one 128B STG per row
    {
        const int warp = tid >> 5;
        const int lane = tid & 31;
        #pragma unroll 4
        for (int r = 0; r < RPB / (TPB / 32); r++) {     // 64 rows per warp
            const int rl   = warp * (RPB / (TPB / 32)) + r;
            const int grow = base + rl;
            if (grow < B) {
                const float4 res = s_res[rl];
                const int pk = __float_as_int(res.w);
                const int i0 = pk & 255, i1 = (pk >> 8) & 255, i2 = (pk >> 16) & 255;
                float val = 0.0f;
                if (lane == i0) val = res.x;
                if (lane == i1) val = res.y;
                if (lane == i2) val = res.z;
                act[(size_t)grow * NB + lane] = val;
            }
        }
    }

    // ---- coalesced assignments
    #pragma unroll
    for (int rl = tid; rl < RPB; rl += TPB) {
        const int grow = base + rl;
        if (grow < B)
            assign[grow] = (float)(__float_as_int(s_res[rl].w) & 255);
    }

    if (tid < NB) {
        const int cnt = s_hist[tid];
        if (cnt) atomicAdd(&util[tid], (float)cnt);
    }
}

extern "C" void kernel_launch(void* const* d_in, const int* in_sizes, int n_in,
                              void* d_out, int out_size) {
    const float* z      = (const float*)d_in[0];
    const float* protos = (const float*)d_in[1];
    const float* u_in   = (const float*)d_in[2];

    const int B = in_sizes[0] / CD;

    float* out    = (float*)d_out;
    float* act    = out;
    float* assign = out + (size_t)B * NB;
    float* util   = out + (size_t)B * (NB + 1);

    gc_init_util<<<1, 32>>>(u_in, util);

    const int grid = (B + RPB - 1) / RPB;
    gc_main<<<grid, TPB>>>(z, protos, act, assign, util, B);
}

// round 5
// speedup vs baseline: 1.0312x; 1.0312x over previous
#include <cuda_runtime.h>
#include <math.h>

#define NB 32
#define CD 64
#define TPB 384
#define RPB 384            // rows per block; 192 pairs x 2 rows
#define NPAIR (TPB / 2)

// ---- packed fp32x2 helpers (Blackwell) ----
__device__ __forceinline__ void fma2(unsigned long long& d,
                                     unsigned long long a,
                                     unsigned long long b) {
    asm("fma.rn.f32x2 %0, %1, %2, %0;" : "+l"(d) : "l"(a), "l"(b));
}
__device__ __forceinline__ unsigned long long splat2(float x) {
    unsigned long long r;
    unsigned int u = __float_as_uint(x);
    asm("mov.b64 %0, {%1, %1};" : "=l"(r) : "r"(u));
    return r;
}
__device__ __forceinline__ void unpack2(unsigned long long v, float& lo, float& hi) {
    unsigned int a, b;
    asm("mov.b64 {%0, %1}, %2;" : "=r"(a), "=r"(b) : "l"(v));
    lo = __uint_as_float(a);
    hi = __uint_as_float(b);
}

__global__ void gc_init_util(const float* __restrict__ u_in,
                             float* __restrict__ u_out) {
    int i = threadIdx.x;
    if (i < NB) u_out[i] = u_in[i];
}

__global__ __launch_bounds__(TPB, 2)
void gc_main(const float* __restrict__ z,
             const float* __restrict__ protos,
             float* __restrict__ act,
             float* __restrict__ assign,
             float* __restrict__ util,
             int B) {
    __shared__ float4      s_z[RPB * 16];      // 96 KB: full 64-d tile, swizzled
    __shared__ ulonglong2  s_pp[CD * 8];       // 8 KB: [d][8x ull2] = 16 basin-pairs
    __shared__ float4      s_res[RPB];         // 6 KB
    __shared__ int         s_hist[NB];

    const int tid  = threadIdx.x;
    const int base = blockIdx.x * RPB;
    const int p    = tid >> 1;          // pair id 0..191
    const int half = tid & 1;           // 0: basins 0-15, 1: basins 16-31

    // ---- packed prototype table: float2[d*16+k] = (proto[2k][d], proto[2k+1][d])
    {
        float2* f2 = (float2*)s_pp;
        for (int idx = tid; idx < CD * 16; idx += TPB) {
            int d = idx >> 4;
            int k = idx & 15;
            f2[idx] = make_float2(protos[(2 * k) * CD + d],
                                  protos[(2 * k + 1) * CD + d]);
        }
        if (tid < NB) s_hist[tid] = 0;
    }

    // ---- stage the full z tile once: coalesced LDG.128, swizzled STS
    #pragma unroll
    for (int it = 0; it < 16; it++) {
        int idx   = it * TPB + tid;
        int row_l = idx >> 4;
        int d4    = idx & 15;
        int grow  = base + row_l;
        if (grow < B) {
            float4 v = *(const float4*)(z + (size_t)grow * CD + d4 * 4);
            s_z[row_l * 16 + (d4 ^ (row_l & 15))] = v;
        }
    }
    __syncthreads();

    // acc[j*8+k]: row j (p + j*NPAIR), basin pair (half*8 + k)
    unsigned long long accA[8], accB[8];
    #pragma unroll
    for (int k = 0; k < 8; k++) { accA[k] = 0ull; accB[k] = 0ull; }

    const int pk15 = p & 15;
    const float4* zr0 = &s_z[p * 16];
    const float4* zr1 = &s_z[(p + NPAIR) * 16];

    #pragma unroll 4
    for (int d4 = 0; d4 < 16; d4++) {
        const int col = d4 ^ pk15;
        const float4 a4 = zr0[col];
        const float4 b4 = zr1[col];
        const float ae[4] = {a4.x, a4.y, a4.z, a4.w};
        const float be[4] = {b4.x, b4.y, b4.z, b4.w};
        #pragma unroll
        for (int e = 0; e < 4; e++) {
            const int d = d4 * 4 + e;
            const ulonglong2* pp = &s_pp[d * 8 + half * 4];
            const unsigned long long za = splat2(ae[e]);
            const unsigned long long zb = splat2(be[e]);
            #pragma unroll
            for (int q = 0; q < 4; q++) {
                ulonglong2 w = pp[q];        // 2 basin pairs; 2 addrs/warp (broadcast)
                fma2(accA[2 * q],     za, w.x);
                fma2(accA[2 * q + 1], za, w.y);
                fma2(accB[2 * q],     zb, w.x);
                fma2(accB[2 * q + 1], zb, w.y);
            }
        }
    }

    // ---- per-row: local top-3 over own 16 basins, shfl-merge with partner lane
    #pragma unroll
    for (int j = 0; j < 2; j++) {
        const int rl  = p + j * NPAIR;
        const bool ok = (base + rl) < B;

        float v[16];
        #pragma unroll
        for (int k = 0; k < 8; k++)
            unpack2(j ? accB[k] : accA[k], v[2 * k], v[2 * k + 1]);

        float l0 = -2.0f, l1 = -2.0f, l2 = -2.0f;
        int   j0 = 0,     j1 = 0,     j2 = 0;
        #pragma unroll
        for (int n = 0; n < 16; n++) {
            const float x = v[n];
            if (x > l2) {
                if (x > l1) {
                    if (x > l0) { l2 = l1; j2 = j1; l1 = l0; j1 = j0; l0 = x; j0 = n; }
                    else        { l2 = l1; j2 = j1; l1 = x;  j1 = n; }
                } else          { l2 = x;  j2 = n; }
            }
        }
        const int g0 = j0 + (half << 4);
        const int g1 = j1 + (half << 4);
        const int g2 = j2 + (half << 4);

        const float q0 = __shfl_xor_sync(0xFFFFFFFFu, l0, 1);
        const float q1 = __shfl_xor_sync(0xFFFFFFFFu, l1, 1);
        const float q2 = __shfl_xor_sync(0xFFFFFFFFu, l2, 1);
        const int   qp = __shfl_xor_sync(0xFFFFFFFFu, g0 | (g1 << 8) | (g2 << 16), 1);

        // a = low-half candidates (ties prefer a, matching stable top_k)
        const float a0 = half ? q0 : l0, a1 = half ? q1 : l1, a2 = half ? q2 : l2;
        const float b0 = half ? l0 : q0, b1 = half ? l1 : q1, b2 = half ? l2 : q2;
        const int ia0 = half ? (qp & 255)        : g0;
        const int ia1 = half ? ((qp >> 8) & 255) : g1;
        const int ia2 = half ? ((qp >> 16) & 255): g2;
        const int ib0 = half ? g0 : (qp & 255);
        const int ib1 = half ? g1 : ((qp >> 8) & 255);
        const int ib2 = half ? g2 : ((qp >> 16) & 255);

        const bool s0 = (a0 >= b0);
        const float m0 = s0 ? a0 : b0;  const int mi0 = s0 ? ia0 : ib0;
        const float ha = s0 ? a1 : a0;  const int hai = s0 ? ia1 : ia0;
        const float hb = s0 ? b0 : b1;  const int hbi = s0 ? ib0 : ib1;
        const bool s1 = (ha >= hb);
        const float m1 = s1 ? ha : hb;  const int mi1 = s1 ? hai : hbi;
        const float ha2 = s1 ? (s0 ? a2 : a1) : ha;
        const int   hai2= s1 ? (s0 ? ia2: ia1): hai;
        const float hb2 = s1 ? hb : (s0 ? b1 : b2);
        const int   hbi2= s1 ? hbi: (s0 ? ib1: ib2);
        const bool s2 = (ha2 >= hb2);
        const float m2 = s2 ? ha2 : hb2; const int mi2 = s2 ? hai2 : hbi2;

        if (half == 0 && ok) {
            const float x1  = __expf((m1 - m0) * 0.2f);
            const float x2  = __expf((m2 - m0) * 0.2f);
            const float inv = 1.0f / (1.0f + x1 + x2);
            s_res[rl] = make_float4(inv, x1 * inv, x2 * inv,
                                    __int_as_float(mi0 | (mi1 << 8) | (mi2 << 16)));
            atomicAdd(&s_hist[mi0], 1);
        }
    }
    __syncthreads();

    // ---- coalesced act stores: one 128B STG per row
    {
        const int warp = tid >> 5;
        const int lane = tid & 31;
        #pragma unroll 4
        for (int r = 0; r < RPB / (TPB / 32); r++) {     // 32 rows per warp
            const int rl   = warp * (RPB / (TPB / 32)) + r;
            const int grow = base + rl;
            if (grow < B) {
                const float4 res = s_res[rl];
                const int pk = __float_as_int(res.w);
                const int i0 = pk & 255, i1 = (pk >> 8) & 255, i2 = (pk >> 16) & 255;
                float val = 0.0f;
                if (lane == i0) val = res.x;
                if (lane == i1) val = res.y;
                if (lane == i2) val = res.z;
                act[(size_t)grow * NB + lane] = val;
            }
        }
    }

    // ---- coalesced assignments (one row per thread)
    {
        const int grow = base + tid;
        if (grow < B)
            assign[grow] = (float)(__float_as_int(s_res[tid].w) & 255);
    }

    if (tid < NB) {
        const int cnt = s_hist[tid];
        if (cnt) atomicAdd(&util[tid], (float)cnt);
    }
}

extern "C" void kernel_launch(void* const* d_in, const int* in_sizes, int n_in,
                              void* d_out, int out_size) {
    const float* z      = (const float*)d_in[0];
    const float* protos = (const float*)d_in[1];
    const float* u_in   = (const float*)d_in[2];

    const int B = in_sizes[0] / CD;

    float* out    = (float*)d_out;
    float* act    = out;
    float* assign = out + (size_t)B * NB;
    float* util   = out + (size_t)B * (NB + 1);

    gc_init_util<<<1, 32>>>(u_in, util);

    const int grid = (B + RPB - 1) / RPB;
    gc_main<<<grid, TPB>>>(z, protos, act, assign, util, B);
}